// round 7
// baseline (speedup 1.0000x reference)
#include <cuda_runtime.h>
#include <cuda_fp16.h>
#include <cstdint>

// ---------------- problem constants ----------------
#define B_     64
#define CIN_   64
#define L_     4096
#define COUT_  128
#define K_     7
#define LOUT_  2048

// ---------------- tiling ----------------
#define TILE_L  192                 // l positions per CTA tile
#define LT_PB   22                  // ceil(4096/192); last tile ragged (64 l)
#define NTILES  (B_ * LT_PB)        // 1408
#define ROWS    198                 // TILE_L + 6 halo
#define NTHR    384                 // 8 MMA warps + 4 producer warps
#define NMMA_W  8
#define GRID    148
#define NCHUNK  50                  // 16B l-chunks per cin (l0-4 .. l0+195)
#define NOPS    (CIN_ * NCHUNK)     // 3200

// ---------------- smem layout ----------------
// A: weights 7 x [128 cout x 64 cin] fp16, 128B rows + SW128 XOR swizzle.
// B: sign tile x2 ping-pong, [198 l-rows x 64 cin] fp16, stride 72 halfs
//    (144B) -> ldmatrix row addrs 4 banks apart: conflict-free.
#define SB_STRIDE 72
#define SM_A      0
#define SM_A_SZ   (K_ * COUT_ * CIN_ * 2)     // 114688
#define SM_B      SM_A_SZ
#define SB_BUF    (ROWS * SB_STRIDE * 2)      // 28512
#define SM_BN     (SM_B + 2 * SB_BUF)         // 171712
#define SM_TOTAL  (SM_BN + 512)               // 172224

// ---------------- PTX helpers ----------------
__device__ __forceinline__ uint32_t smem_u32(const void* p) {
    uint32_t a;
    asm("{ .reg .u64 t; cvta.to.shared.u64 t, %1; cvt.u32.u64 %0, t; }"
        : "=r"(a) : "l"(p));
    return a;
}
__device__ __forceinline__ void ldsm4(uint32_t* r, uint32_t a) {
    asm volatile("ldmatrix.sync.aligned.m8n8.x4.shared.b16 {%0,%1,%2,%3}, [%4];"
        : "=r"(r[0]), "=r"(r[1]), "=r"(r[2]), "=r"(r[3]) : "r"(a));
}
__device__ __forceinline__ void mma16816(float* d,
                                         uint32_t a0, uint32_t a1, uint32_t a2, uint32_t a3,
                                         uint32_t b0, uint32_t b1) {
    asm volatile("mma.sync.aligned.m16n8k16.row.col.f32.f16.f16.f32 "
                 "{%0,%1,%2,%3}, {%4,%5,%6,%7}, {%8,%9}, {%0,%1,%2,%3};"
                 : "+f"(d[0]), "+f"(d[1]), "+f"(d[2]), "+f"(d[3])
                 : "r"(a0), "r"(a1), "r"(a2), "r"(a3), "r"(b0), "r"(b1));
}
// XOR swizzle on byte offsets within A (128B rows)
__device__ __forceinline__ uint32_t swA(uint32_t o) { return o ^ ((o >> 3) & 0x70); }

// ---------------- kernel ----------------
// Persistent CTAs, warp-specialized:
//   warps 0-7  : MMA (warp tile 64 cout x 48 l) + fused epilogue
//   warps 8-11 : produce sign tile for the NEXT iteration (LDG->BN->sign->STS)
// One __syncthreads per tile swaps the ping-pong sign buffer.
//
// B fragments come from NON-trans ldmatrix on the [l][cin] tile:
// stored row l = fragment n, stored col cin = fragment k, so lane t gets
// {store[t/4][2(t%4)], +1} = {B[k=2(t%4)][n=t/4], B[k+1][n]} as required.
__global__ __launch_bounds__(NTHR, 1)
void bn_bin_conv_pool_ws(const float* __restrict__ I,
                         const float* __restrict__ bn_gamma,
                         const float* __restrict__ bn_beta,
                         const float* __restrict__ bn_mean,
                         const float* __restrict__ bn_var,
                         const float* __restrict__ conv_w,
                         const float* __restrict__ alpha,
                         const float* __restrict__ prelu_w,
                         float* __restrict__ out)
{
    extern __shared__ __align__(16) char smem[];
    const uint32_t sm0 = smem_u32(smem);
    float* sa  = (float*)(smem + SM_BN);
    float* sbn = sa + CIN_;

    const int tid  = threadIdx.x;
    const int lane = tid & 31;
    const int wid  = tid >> 5;
    const bool is_mma = (wid < NMMA_W);
    const int wh = is_mma ? (wid >> 2) : 0;   // cout half (0..1)
    const int wq = is_mma ? (wid & 3)  : 0;   // l quarter (48 l each)
    const int r  = lane >> 2;
    const int q  = lane & 3;

    // BN fold: v = sa*x + sbn
    if (tid < CIN_) {
        float a = bn_gamma[tid] * rsqrtf(bn_var[tid] + 1e-5f);
        sa[tid]  = a;
        sbn[tid] = bn_beta[tid] - bn_mean[tid] * a;
    }

    // Weights -> fp16, [tap][cout][cin] 128B rows, SW128 swizzle (once)
    for (int idx = tid; idx < COUT_ * CIN_ * K_; idx += NTHR) {
        int k    = idx % K_;
        int rest = idx / K_;
        int cin  = rest & (CIN_ - 1);
        int cout = rest >> 6;
        uint32_t off = (uint32_t)((((k * COUT_ + cout) * CIN_) + cin) * 2);
        *(__half*)(smem + SM_A + swA(off)) = __float2half(conv_w[idx]);
    }

    // A ldmatrix lane addressing: tiles (m0-7,k0-7),(m8-15,k0-7),(m0-7,k8-15),(m8-15,k8-15)
    const int jj = lane >> 3, ii = lane & 7;
    const int a_row  = (jj & 1) * 8 + ii;
    const int a_colh = (jj >> 1) * 8;
    // B ldmatrix (non-trans) lane addressing:
    // tiles (n0-7,k0-7),(n0-7,k8-15),(n8-15,k0-7),(n8-15,k8-15)
    const int b_rowc = ((lane >> 4) & 1) * 8 + (lane & 7);  // l row offset
    const int b_kh   = ((lane >> 3) & 1) * 8;               // cin half offset

    float al[4][2];
    if (is_mma) {
        #pragma unroll
        for (int mf = 0; mf < 4; mf++) {
            al[mf][0] = alpha[wh * 64 + mf * 16 + r];
            al[mf][1] = alpha[wh * 64 + mf * 16 + r + 8];
        }
    }
    const float pw = prelu_w[0];

    // ---- sign-tile producer: tile t -> smem byte offset sbOff ----
    auto convert = [&](int t, uint32_t sbOff, int id, int np) {
        int bb = t / LT_PB;
        int l0 = (t - bb * LT_PB) * TILE_L;
        const float* Ib = I + (size_t)bb * CIN_ * L_;
        #pragma unroll 2
        for (int o = id; o < NOPS; o += np) {
            int cin = o / NCHUNK, ch = o - cin * NCHUNK;
            int gl = l0 - 4 + ch * 4;
            float aa = sa[cin], bv = sbn[cin];
            float x[4];
            bool inb = (gl >= 0) && (gl + 4 <= L_);
            if (inb) {
                float4 v = *(const float4*)(Ib + (size_t)cin * L_ + gl);
                x[0] = v.x; x[1] = v.y; x[2] = v.z; x[3] = v.w;
            }
            #pragma unroll
            for (int j = 0; j < 4; j++) {
                int rr = ch * 4 + j - 1;           // sign-tile row
                if ((unsigned)rr < (unsigned)ROWS) {
                    int l = gl + j;
                    float s = 0.f;
                    if ((unsigned)l < (unsigned)L_) {
                        float xx = inb ? x[j] : Ib[(size_t)cin * L_ + l];
                        float vv = fmaf(aa, xx, bv);
                        s = (vv > 0.f) ? 1.f : ((vv < 0.f) ? -1.f : 0.f);
                    }
                    *(__half*)(smem + sbOff + (uint32_t)((rr * SB_STRIDE + cin) * 2))
                        = __float2half(s);
                }
            }
        }
    };

    // ---- prologue: all threads fill buffer 0 for the first tile ----
    __syncthreads();                 // BN + weights visible
    if (blockIdx.x < NTILES) convert(blockIdx.x, SM_B, tid, NTHR);
    __syncthreads();

    int cur = 0;
    for (int t = blockIdx.x; t < NTILES; t += GRID) {
        const int tn = t + GRID;

        if (is_mma) {
            const int bb = t / LT_PB;
            const int l0 = (t - bb * LT_PB) * TILE_L;
            const uint32_t sBu = sm0 + SM_B + (uint32_t)(cur * SB_BUF);

            float acc[4][6][4];
            #pragma unroll
            for (int mf = 0; mf < 4; mf++)
                #pragma unroll
                for (int nf = 0; nf < 6; nf++)
                    #pragma unroll
                    for (int e = 0; e < 4; e++) acc[mf][nf][e] = 0.f;

            #pragma unroll
            for (int k = 0; k < K_; k++) {
                #pragma unroll
                for (int c = 0; c < 4; c++) {
                    uint32_t af[4][4];
                    #pragma unroll
                    for (int mf = 0; mf < 4; mf++) {
                        uint32_t o = (uint32_t)((((k * COUT_ + wh * 64 + mf * 16 + a_row)
                                      * CIN_) + c * 16 + a_colh) * 2);
                        ldsm4(af[mf], sm0 + SM_A + swA(o));
                    }
                    uint32_t bf[3][4];
                    #pragma unroll
                    for (int p = 0; p < 3; p++) {
                        uint32_t brow = (uint32_t)(wq * 48 + p * 16 + b_rowc + k);
                        ldsm4(bf[p], sBu + brow * (SB_STRIDE * 2)
                                         + (uint32_t)((c * 16 + b_kh) * 2));
                    }
                    // bf[p] regs: r0=(n0-7,k0-7) r1=(n0-7,k8-15) r2=(n8-15,k0-7) r3=(n8-15,k8-15)
                    #pragma unroll
                    for (int p = 0; p < 3; p++)
                        #pragma unroll
                        for (int h = 0; h < 2; h++) {
                            uint32_t b0 = bf[p][2 * h], b1 = bf[p][2 * h + 1];
                            #pragma unroll
                            for (int mf = 0; mf < 4; mf++)
                                mma16816(acc[mf][2 * p + h],
                                         af[mf][0], af[mf][1], af[mf][2], af[mf][3],
                                         b0, b1);
                        }
                }
            }

            // epilogue: alpha, PReLU, maxpool(2,2); ragged-tile guard
            const int lim = (L_ - l0) >> 1;
            float* ob = out + ((size_t)bb * COUT_) * LOUT_ + (l0 >> 1);
            #pragma unroll
            for (int mf = 0; mf < 4; mf++) {
                const int c0 = wh * 64 + mf * 16 + r;
                #pragma unroll
                for (int nf = 0; nf < 6; nf++) {
                    const int lp = wq * 24 + nf * 4 + q;
                    if (lp < lim) {
                        float y0 = acc[mf][nf][0] * al[mf][0];
                        float y1 = acc[mf][nf][1] * al[mf][0];
                        y0 = (y0 > 0.f) ? y0 : pw * y0;
                        y1 = (y1 > 0.f) ? y1 : pw * y1;
                        ob[(size_t)c0 * LOUT_ + lp] = fmaxf(y0, y1);
                        float y2 = acc[mf][nf][2] * al[mf][1];
                        float y3 = acc[mf][nf][3] * al[mf][1];
                        y2 = (y2 > 0.f) ? y2 : pw * y2;
                        y3 = (y3 > 0.f) ? y3 : pw * y3;
                        ob[(size_t)(c0 + 8) * LOUT_ + lp] = fmaxf(y2, y3);
                    }
                }
            }
        } else {
            if (tn < NTILES)
                convert(tn, SM_B + (uint32_t)((cur ^ 1) * SB_BUF), tid - 256, 128);
        }

        __syncthreads();   // buffer handoff: cur consumed, cur^1 filled
        cur ^= 1;
    }
}

// ---------------- launch ----------------
extern "C" void kernel_launch(void* const* d_in, const int* in_sizes, int n_in,
                              void* d_out, int out_size)
{
    const float* I        = (const float*)d_in[0];
    const float* bn_gamma = (const float*)d_in[1];
    const float* bn_beta  = (const float*)d_in[2];
    const float* bn_mean  = (const float*)d_in[3];
    const float* bn_var   = (const float*)d_in[4];
    const float* conv_w   = (const float*)d_in[5];
    const float* alpha    = (const float*)d_in[6];
    const float* prelu_w  = (const float*)d_in[7];
    float* out = (float*)d_out;

    cudaFuncSetAttribute(bn_bin_conv_pool_ws,
                         cudaFuncAttributeMaxDynamicSharedMemorySize, SM_TOTAL);
    bn_bin_conv_pool_ws<<<GRID, NTHR, SM_TOTAL>>>(
        I, bn_gamma, bn_beta, bn_mean, bn_var, conv_w, alpha, prelu_w, out);
}

// round 9
// speedup vs baseline: 1.7635x; 1.7635x over previous
#include <cuda_runtime.h>
#include <cuda_fp16.h>
#include <cstdint>

// ---------------- problem constants ----------------
#define B_     64
#define CIN_   64
#define L_     4096
#define COUT_  128
#define K_     7
#define LOUT_  2048

// ---------------- tiling ----------------
#define TILE_L  192                 // l positions per CTA tile
#define LT_PB   22                  // ceil(4096/192); last tile ragged (64 l)
#define NTILES  (B_ * LT_PB)        // 1408
#define ROWS    198                 // TILE_L + 6 halo
#define NTHR    256                 // 8 warps, all do MMA + convert
#define GRID    148
#define NCHUNK  50                  // 16B l-chunks per cin (l0-4 .. l0+195)
#define NOPS    (CIN_ * NCHUNK)     // 3200

// ---------------- smem layout ----------------
// A: weights 7 x [128 cout x 64 cin] fp16, 128B rows + SW128 XOR swizzle.
// B: sign tile x2 ping-pong, [198 l-rows x 64 cin] fp16, stride 72 halfs
//    (144B) -> ldmatrix row addrs 4 banks apart: conflict-free.
// RAW: cp.async fp32 staging, [64 cin x 204 floats] (stride 204 -> bank step
//    12 per cin: 8-lane LDS.128 phases conflict-free).
#define SB_STRIDE  72
#define RAW_STRIDE 204
#define SM_A      0
#define SM_A_SZ   (K_ * COUT_ * CIN_ * 2)     // 114688
#define SM_B      SM_A_SZ
#define SB_BUF    (ROWS * SB_STRIDE * 2)      // 28512
#define SM_RAW    (SM_B + 2 * SB_BUF)         // 171712 (16B aligned)
#define SM_RAW_SZ (CIN_ * RAW_STRIDE * 4)     // 52224
#define SM_BN     (SM_RAW + SM_RAW_SZ)        // 223936
#define SM_TOTAL  (SM_BN + 512)               // 224448

// ---------------- PTX helpers ----------------
__device__ __forceinline__ uint32_t smem_u32(const void* p) {
    uint32_t a;
    asm("{ .reg .u64 t; cvta.to.shared.u64 t, %1; cvt.u32.u64 %0, t; }"
        : "=r"(a) : "l"(p));
    return a;
}
__device__ __forceinline__ void ldsm4(uint32_t* r, uint32_t a) {
    asm volatile("ldmatrix.sync.aligned.m8n8.x4.shared.b16 {%0,%1,%2,%3}, [%4];"
        : "=r"(r[0]), "=r"(r[1]), "=r"(r[2]), "=r"(r[3]) : "r"(a));
}
__device__ __forceinline__ void mma16816(float* d,
                                         uint32_t a0, uint32_t a1, uint32_t a2, uint32_t a3,
                                         uint32_t b0, uint32_t b1) {
    asm volatile("mma.sync.aligned.m16n8k16.row.col.f32.f16.f16.f32 "
                 "{%0,%1,%2,%3}, {%4,%5,%6,%7}, {%8,%9}, {%0,%1,%2,%3};"
                 : "+f"(d[0]), "+f"(d[1]), "+f"(d[2]), "+f"(d[3])
                 : "r"(a0), "r"(a1), "r"(a2), "r"(a3), "r"(b0), "r"(b1));
}
__device__ __forceinline__ void cp16(uint32_t dst, const void* src, int sz) {
    asm volatile("cp.async.cg.shared.global [%0], [%1], 16, %2;"
                 :: "r"(dst), "l"(src), "r"(sz) : "memory");
}
#define CP_COMMIT() asm volatile("cp.async.commit_group;" ::: "memory")
#define CP_WAIT0()  asm volatile("cp.async.wait_group 0;" ::: "memory")
// XOR swizzle on byte offsets within A (128B rows)
__device__ __forceinline__ uint32_t swA(uint32_t o) { return o ^ ((o >> 3) & 0x70); }

// ---------------- kernel ----------------
// Persistent CTAs, 8 warps all-purpose. Per tile: cp.async prefetch of next
// tile's raw fp32 overlaps MMA; convert runs after the epilogue.
// RACE FIX vs R8: convert reads RAW chunks copied by OTHER threads, so it
// must be CP_WAIT0 (own copies drained) -> __syncthreads (publish all
// threads' copies) -> read. wait_group alone only covers own copies.
// Warp tile = 64 cout x 48 l (mf=4, nf=6).
__global__ __launch_bounds__(NTHR, 1)
void bn_bin_conv_pool_v9(const float* __restrict__ I,
                         const float* __restrict__ bn_gamma,
                         const float* __restrict__ bn_beta,
                         const float* __restrict__ bn_mean,
                         const float* __restrict__ bn_var,
                         const float* __restrict__ conv_w,
                         const float* __restrict__ alpha,
                         const float* __restrict__ prelu_w,
                         float* __restrict__ out)
{
    extern __shared__ __align__(16) char smem[];
    const uint32_t sm0 = smem_u32(smem);
    float* sa  = (float*)(smem + SM_BN);
    float* sbn = sa + CIN_;

    const int tid  = threadIdx.x;
    const int lane = tid & 31;
    const int wid  = tid >> 5;
    const int wh   = wid >> 2;      // cout half (0..1)
    const int wq   = wid & 3;       // l quarter (48 l each)
    const int r    = lane >> 2;
    const int q    = lane & 3;

    // BN fold: v = sa*x + sbn
    if (tid < CIN_) {
        float a = bn_gamma[tid] * rsqrtf(bn_var[tid] + 1e-5f);
        sa[tid]  = a;
        sbn[tid] = bn_beta[tid] - bn_mean[tid] * a;
    }

    // Weights -> fp16, [tap][cout][cin] 128B rows, SW128 swizzle (once)
    for (int idx = tid; idx < COUT_ * CIN_ * K_; idx += NTHR) {
        int k    = idx % K_;
        int rest = idx / K_;
        int cin  = rest & (CIN_ - 1);
        int cout = rest >> 6;
        uint32_t off = (uint32_t)((((k * COUT_ + cout) * CIN_) + cin) * 2);
        *(__half*)(smem + SM_A + swA(off)) = __float2half(conv_w[idx]);
    }

    // A ldmatrix lane addressing: tiles (m0-7,k0-7),(m8-15,k0-7),(m0-7,k8-15),(m8-15,k8-15)
    const int jj = lane >> 3, ii = lane & 7;
    const int a_row  = (jj & 1) * 8 + ii;
    const int a_colh = (jj >> 1) * 8;
    // B ldmatrix (non-trans, validated in R7):
    // tiles (n0-7,k0-7),(n0-7,k8-15),(n8-15,k0-7),(n8-15,k8-15)
    const int b_rowc = ((lane >> 4) & 1) * 8 + (lane & 7);  // l row offset
    const int b_kh   = ((lane >> 3) & 1) * 8;               // cin half offset

    float al[4][2];
    #pragma unroll
    for (int mf = 0; mf < 4; mf++) {
        al[mf][0] = alpha[wh * 64 + mf * 16 + r];
        al[mf][1] = alpha[wh * 64 + mf * 16 + r + 8];
    }
    const float pw = prelu_w[0];

    // ---- cp.async issue: raw fp32 for tile t -> RAW (lanes = consecutive
    //      chunks of one cin: coalesced gmem) ----
    auto issue_raw = [&](int t) {
        int bb = t / LT_PB;
        int l0 = (t - bb * LT_PB) * TILE_L;
        const float* Ib = I + (size_t)bb * CIN_ * L_;
        #pragma unroll 4
        for (int o = tid; o < NOPS; o += NTHR) {
            int cin = o / NCHUNK, ch = o - cin * NCHUNK;
            int gl = l0 - 4 + ch * 4;
            int sz = ((unsigned)gl <= (unsigned)(L_ - 4)) ? 16 : 0;
            int glc = sz ? gl : 0;
            cp16(sm0 + SM_RAW + (uint32_t)((cin * RAW_STRIDE + ch * 4) * 4),
                 Ib + (size_t)cin * L_ + glc, sz);
        }
        CP_COMMIT();
    };

    // ---- convert RAW -> sign tile (lanes = consecutive cin: conflict-free
    //      LDS.128 phases and conflict-free STS.b16). Reads cross-thread
    //      data: drain own group, then barrier, then read. ----
    auto convert = [&](int t, uint32_t sbOff) {
        CP_WAIT0();
        __syncthreads();   // publish ALL threads' cp.async data
        int bb = t / LT_PB;
        int l0 = (t - bb * LT_PB) * TILE_L;
        #pragma unroll 2
        for (int o = tid; o < NOPS; o += NTHR) {
            int cin = o & (CIN_ - 1), ch = o >> 6;
            const float4 v = *(const float4*)(smem + SM_RAW
                                + (size_t)((cin * RAW_STRIDE + ch * 4) * 4));
            float aa = sa[cin], bv = sbn[cin];
            float vv[4] = {v.x, v.y, v.z, v.w};
            #pragma unroll
            for (int j = 0; j < 4; j++) {
                int rr = ch * 4 + j - 1;           // sign-tile row
                if ((unsigned)rr < (unsigned)ROWS) {
                    int l = l0 - 3 + rr;
                    float s = 0.f;
                    if ((unsigned)l < (unsigned)L_) {
                        float x = fmaf(aa, vv[j], bv);
                        s = (x > 0.f) ? 1.f : ((x < 0.f) ? -1.f : 0.f);
                    }
                    *(__half*)(smem + sbOff + (uint32_t)((rr * SB_STRIDE + cin) * 2))
                        = __float2half(s);
                }
            }
        }
    };

    // ---- prologue: fill sign buffer 0 for the first tile ----
    issue_raw(blockIdx.x);
    __syncthreads();                 // BN + weights visible
    convert(blockIdx.x, SM_B);
    __syncthreads();

    int cur = 0;
    for (int t = blockIdx.x; t < NTILES; t += GRID) {
        const int bb = t / LT_PB;
        const int l0 = (t - bb * LT_PB) * TILE_L;
        const int tn = t + GRID;

        if (tn < NTILES) issue_raw(tn);   // overlaps MMA below

        const uint32_t sBu = sm0 + SM_B + (uint32_t)(cur * SB_BUF);

        float acc[4][6][4];
        #pragma unroll
        for (int mf = 0; mf < 4; mf++)
            #pragma unroll
            for (int nf = 0; nf < 6; nf++)
                #pragma unroll
                for (int e = 0; e < 4; e++) acc[mf][nf][e] = 0.f;

        #pragma unroll
        for (int k = 0; k < K_; k++) {
            #pragma unroll
            for (int c = 0; c < 4; c++) {
                uint32_t af[4][4];
                #pragma unroll
                for (int mf = 0; mf < 4; mf++) {
                    uint32_t o = (uint32_t)((((k * COUT_ + wh * 64 + mf * 16 + a_row)
                                  * CIN_) + c * 16 + a_colh) * 2);
                    ldsm4(af[mf], sm0 + SM_A + swA(o));
                }
                uint32_t bf[3][4];
                #pragma unroll
                for (int p = 0; p < 3; p++) {
                    uint32_t brow = (uint32_t)(wq * 48 + p * 16 + b_rowc + k);
                    ldsm4(bf[p], sBu + brow * (SB_STRIDE * 2)
                                     + (uint32_t)((c * 16 + b_kh) * 2));
                }
                #pragma unroll
                for (int p = 0; p < 3; p++)
                    #pragma unroll
                    for (int h = 0; h < 2; h++) {
                        uint32_t b0 = bf[p][2 * h], b1 = bf[p][2 * h + 1];
                        #pragma unroll
                        for (int mf = 0; mf < 4; mf++)
                            mma16816(acc[mf][2 * p + h],
                                     af[mf][0], af[mf][1], af[mf][2], af[mf][3],
                                     b0, b1);
                    }
            }
        }

        // epilogue: alpha, PReLU, maxpool(2,2); ragged-tile guard
        const int lim = (L_ - l0) >> 1;
        float* ob = out + ((size_t)bb * COUT_) * LOUT_ + (l0 >> 1);
        #pragma unroll
        for (int mf = 0; mf < 4; mf++) {
            const int c0 = wh * 64 + mf * 16 + r;
            #pragma unroll
            for (int nf = 0; nf < 6; nf++) {
                const int lp = wq * 24 + nf * 4 + q;
                if (lp < lim) {
                    float y0 = acc[mf][nf][0] * al[mf][0];
                    float y1 = acc[mf][nf][1] * al[mf][0];
                    y0 = (y0 > 0.f) ? y0 : pw * y0;
                    y1 = (y1 > 0.f) ? y1 : pw * y1;
                    ob[(size_t)c0 * LOUT_ + lp] = fmaxf(y0, y1);
                    float y2 = acc[mf][nf][2] * al[mf][1];
                    float y3 = acc[mf][nf][3] * al[mf][1];
                    y2 = (y2 > 0.f) ? y2 : pw * y2;
                    y3 = (y3 > 0.f) ? y3 : pw * y3;
                    ob[(size_t)(c0 + 8) * LOUT_ + lp] = fmaxf(y2, y3);
                }
            }
        }

        if (tn < NTILES) convert(tn, SM_B + (uint32_t)((cur ^ 1) * SB_BUF));
        __syncthreads();   // buffer handoff + RAW reuse + sB read-complete
        cur ^= 1;
    }
}

// ---------------- launch ----------------
extern "C" void kernel_launch(void* const* d_in, const int* in_sizes, int n_in,
                              void* d_out, int out_size)
{
    const float* I        = (const float*)d_in[0];
    const float* bn_gamma = (const float*)d_in[1];
    const float* bn_beta  = (const float*)d_in[2];
    const float* bn_mean  = (const float*)d_in[3];
    const float* bn_var   = (const float*)d_in[4];
    const float* conv_w   = (const float*)d_in[5];
    const float* alpha    = (const float*)d_in[6];
    const float* prelu_w  = (const float*)d_in[7];
    float* out = (float*)d_out;

    cudaFuncSetAttribute(bn_bin_conv_pool_v9,
                         cudaFuncAttributeMaxDynamicSharedMemorySize, SM_TOTAL);
    bn_bin_conv_pool_v9<<<GRID, NTHR, SM_TOTAL>>>(
        I, bn_gamma, bn_beta, bn_mean, bn_var, conv_w, alpha, prelu_w, out);
}

// round 10
// speedup vs baseline: 1.9793x; 1.1224x over previous
#include <cuda_runtime.h>
#include <cuda_fp16.h>
#include <cstdint>

// ---------------- problem constants ----------------
#define B_     64
#define CIN_   64
#define L_     4096
#define COUT_  128
#define K_     7
#define LOUT_  2048

// ---------------- tiling ----------------
#define TILE_L  192                 // l positions per CTA tile
#define LT_PB   22                  // ceil(4096/192); last tile ragged (64 l)
#define NTILES  (B_ * LT_PB)        // 1408
#define ROWS    198                 // TILE_L + 6 halo
#define NTHR    512                 // 16 warps: 4 cout quarters x 4 l quarters
#define GRID    148
#define NCHUNK  50                  // 16B l-chunks per cin (l0-4 .. l0+195)
#define NOPS    (CIN_ * NCHUNK)     // 3200

// ---------------- smem layout ----------------
// A: weights 7 x [128 cout x 64 cin] fp16, 128B rows + SW128 XOR swizzle.
// B: sign tile x2 ping-pong, [198 l-rows x 64 cin] fp16, stride 72 halfs
//    (144B) -> ldmatrix row addrs 4 banks apart: conflict-free.
// RAW: cp.async fp32 staging, [64 cin x 204 floats] (bank step 12/cin:
//    8-lane LDS.128 phases conflict-free).
#define SB_STRIDE  72
#define RAW_STRIDE 204
#define SM_A      0
#define SM_A_SZ   (K_ * COUT_ * CIN_ * 2)     // 114688
#define SM_B      SM_A_SZ
#define SB_BUF    (ROWS * SB_STRIDE * 2)      // 28512
#define SM_RAW    (SM_B + 2 * SB_BUF)         // 171712 (16B aligned)
#define SM_RAW_SZ (CIN_ * RAW_STRIDE * 4)     // 52224
#define SM_BN     (SM_RAW + SM_RAW_SZ)        // 223936
#define SM_TOTAL  (SM_BN + 512)               // 224448

// ---------------- PTX helpers ----------------
__device__ __forceinline__ uint32_t smem_u32(const void* p) {
    uint32_t a;
    asm("{ .reg .u64 t; cvta.to.shared.u64 t, %1; cvt.u32.u64 %0, t; }"
        : "=r"(a) : "l"(p));
    return a;
}
__device__ __forceinline__ void ldsm4(uint32_t* r, uint32_t a) {
    asm volatile("ldmatrix.sync.aligned.m8n8.x4.shared.b16 {%0,%1,%2,%3}, [%4];"
        : "=r"(r[0]), "=r"(r[1]), "=r"(r[2]), "=r"(r[3]) : "r"(a));
}
__device__ __forceinline__ void mma16816(float* d,
                                         uint32_t a0, uint32_t a1, uint32_t a2, uint32_t a3,
                                         uint32_t b0, uint32_t b1) {
    asm volatile("mma.sync.aligned.m16n8k16.row.col.f32.f16.f16.f32 "
                 "{%0,%1,%2,%3}, {%4,%5,%6,%7}, {%8,%9}, {%0,%1,%2,%3};"
                 : "+f"(d[0]), "+f"(d[1]), "+f"(d[2]), "+f"(d[3])
                 : "r"(a0), "r"(a1), "r"(a2), "r"(a3), "r"(b0), "r"(b1));
}
__device__ __forceinline__ void cp16(uint32_t dst, const void* src, int sz) {
    asm volatile("cp.async.cg.shared.global [%0], [%1], 16, %2;"
                 :: "r"(dst), "l"(src), "r"(sz) : "memory");
}
#define CP_COMMIT() asm volatile("cp.async.commit_group;" ::: "memory")
#define CP_WAIT0()  asm volatile("cp.async.wait_group 0;" ::: "memory")
// XOR swizzle on byte offsets within A (128B rows)
__device__ __forceinline__ uint32_t swA(uint32_t o) { return o ^ ((o >> 3) & 0x70); }

// ---------------- kernel ----------------
// Persistent CTAs, 16 warps all-purpose. Warp tile = 32 cout x 48 l
// (mf=2, nf=6, acc 48 regs) -> 4 warps/SMSP for latency hiding and 2x
// parallel convert/epilogue vs R9. Same validated mainloop + cp.async
// pipeline with the R9 visibility fix.
__global__ __launch_bounds__(NTHR, 1)
void bn_bin_conv_pool_v10(const float* __restrict__ I,
                          const float* __restrict__ bn_gamma,
                          const float* __restrict__ bn_beta,
                          const float* __restrict__ bn_mean,
                          const float* __restrict__ bn_var,
                          const float* __restrict__ conv_w,
                          const float* __restrict__ alpha,
                          const float* __restrict__ prelu_w,
                          float* __restrict__ out)
{
    extern __shared__ __align__(16) char smem[];
    const uint32_t sm0 = smem_u32(smem);
    float* sa  = (float*)(smem + SM_BN);
    float* sbn = sa + CIN_;

    const int tid  = threadIdx.x;
    const int lane = tid & 31;
    const int wid  = tid >> 5;
    const int wc   = wid >> 2;      // cout quarter (0..3): 32 couts
    const int wl   = wid & 3;       // l quarter    (0..3): 48 l
    const int r    = lane >> 2;
    const int q    = lane & 3;

    // BN fold: v = sa*x + sbn
    if (tid < CIN_) {
        float a = bn_gamma[tid] * rsqrtf(bn_var[tid] + 1e-5f);
        sa[tid]  = a;
        sbn[tid] = bn_beta[tid] - bn_mean[tid] * a;
    }

    // Weights -> fp16, [tap][cout][cin] 128B rows, SW128 swizzle (once)
    for (int idx = tid; idx < COUT_ * CIN_ * K_; idx += NTHR) {
        int k    = idx % K_;
        int rest = idx / K_;
        int cin  = rest & (CIN_ - 1);
        int cout = rest >> 6;
        uint32_t off = (uint32_t)((((k * COUT_ + cout) * CIN_) + cin) * 2);
        *(__half*)(smem + SM_A + swA(off)) = __float2half(conv_w[idx]);
    }

    // A ldmatrix lane addressing: tiles (m0-7,k0-7),(m8-15,k0-7),(m0-7,k8-15),(m8-15,k8-15)
    const int jj = lane >> 3, ii = lane & 7;
    const int a_row  = (jj & 1) * 8 + ii;
    const int a_colh = (jj >> 1) * 8;
    // B ldmatrix (non-trans, validated in R7):
    // tiles (n0-7,k0-7),(n0-7,k8-15),(n8-15,k0-7),(n8-15,k8-15)
    const int b_rowc = ((lane >> 4) & 1) * 8 + (lane & 7);  // l row offset
    const int b_kh   = ((lane >> 3) & 1) * 8;               // cin half offset

    float al[2][2];
    #pragma unroll
    for (int mf = 0; mf < 2; mf++) {
        al[mf][0] = alpha[wc * 32 + mf * 16 + r];
        al[mf][1] = alpha[wc * 32 + mf * 16 + r + 8];
    }
    const float pw = prelu_w[0];

    // ---- cp.async issue: raw fp32 for tile t -> RAW (lanes = consecutive
    //      chunks of one cin: coalesced gmem) ----
    auto issue_raw = [&](int t) {
        int bb = t / LT_PB;
        int l0 = (t - bb * LT_PB) * TILE_L;
        const float* Ib = I + (size_t)bb * CIN_ * L_;
        #pragma unroll 4
        for (int o = tid; o < NOPS; o += NTHR) {
            int cin = o / NCHUNK, ch = o - cin * NCHUNK;
            int gl = l0 - 4 + ch * 4;
            int sz = ((unsigned)gl <= (unsigned)(L_ - 4)) ? 16 : 0;
            int glc = sz ? gl : 0;
            cp16(sm0 + SM_RAW + (uint32_t)((cin * RAW_STRIDE + ch * 4) * 4),
                 Ib + (size_t)cin * L_ + glc, sz);
        }
        CP_COMMIT();
    };

    // ---- convert RAW -> sign tile (lanes = consecutive cin: conflict-free
    //      LDS.128 phases and STS.b16). Cross-thread reads: drain own
    //      group, then barrier, then read (R9 race fix). ----
    auto convert = [&](int t, uint32_t sbOff) {
        CP_WAIT0();
        __syncthreads();   // publish ALL threads' cp.async data
        int bb = t / LT_PB;
        int l0 = (t - bb * LT_PB) * TILE_L;
        #pragma unroll 2
        for (int o = tid; o < NOPS; o += NTHR) {
            int cin = o & (CIN_ - 1), ch = o >> 6;
            const float4 v = *(const float4*)(smem + SM_RAW
                                + (size_t)((cin * RAW_STRIDE + ch * 4) * 4));
            float aa = sa[cin], bv = sbn[cin];
            float vv[4] = {v.x, v.y, v.z, v.w};
            #pragma unroll
            for (int j = 0; j < 4; j++) {
                int rr = ch * 4 + j - 1;           // sign-tile row
                if ((unsigned)rr < (unsigned)ROWS) {
                    int l = l0 - 3 + rr;
                    float s = 0.f;
                    if ((unsigned)l < (unsigned)L_) {
                        float x = fmaf(aa, vv[j], bv);
                        s = (x > 0.f) ? 1.f : ((x < 0.f) ? -1.f : 0.f);
                    }
                    *(__half*)(smem + sbOff + (uint32_t)((rr * SB_STRIDE + cin) * 2))
                        = __float2half(s);
                }
            }
        }
    };

    // ---- prologue: fill sign buffer 0 for the first tile ----
    issue_raw(blockIdx.x);
    __syncthreads();                 // BN + weights visible
    convert(blockIdx.x, SM_B);
    __syncthreads();

    int cur = 0;
    for (int t = blockIdx.x; t < NTILES; t += GRID) {
        const int bb = t / LT_PB;
        const int l0 = (t - bb * LT_PB) * TILE_L;
        const int tn = t + GRID;

        if (tn < NTILES) issue_raw(tn);   // overlaps MMA below

        const uint32_t sBu = sm0 + SM_B + (uint32_t)(cur * SB_BUF);

        float acc[2][6][4];
        #pragma unroll
        for (int mf = 0; mf < 2; mf++)
            #pragma unroll
            for (int nf = 0; nf < 6; nf++)
                #pragma unroll
                for (int e = 0; e < 4; e++) acc[mf][nf][e] = 0.f;

        #pragma unroll
        for (int k = 0; k < K_; k++) {
            #pragma unroll
            for (int c = 0; c < 4; c++) {
                uint32_t af[2][4];
                #pragma unroll
                for (int mf = 0; mf < 2; mf++) {
                    uint32_t o = (uint32_t)((((k * COUT_ + wc * 32 + mf * 16 + a_row)
                                  * CIN_) + c * 16 + a_colh) * 2);
                    ldsm4(af[mf], sm0 + SM_A + swA(o));
                }
                uint32_t bf[3][4];
                #pragma unroll
                for (int p = 0; p < 3; p++) {
                    uint32_t brow = (uint32_t)(wl * 48 + p * 16 + b_rowc + k);
                    ldsm4(bf[p], sBu + brow * (SB_STRIDE * 2)
                                     + (uint32_t)((c * 16 + b_kh) * 2));
                }
                #pragma unroll
                for (int p = 0; p < 3; p++)
                    #pragma unroll
                    for (int h = 0; h < 2; h++) {
                        uint32_t b0 = bf[p][2 * h], b1 = bf[p][2 * h + 1];
                        #pragma unroll
                        for (int mf = 0; mf < 2; mf++)
                            mma16816(acc[mf][2 * p + h],
                                     af[mf][0], af[mf][1], af[mf][2], af[mf][3],
                                     b0, b1);
                    }
            }
        }

        // epilogue: alpha, PReLU, maxpool(2,2); ragged-tile guard
        const int lim = (L_ - l0) >> 1;
        float* ob = out + ((size_t)bb * COUT_) * LOUT_ + (l0 >> 1);
        #pragma unroll
        for (int mf = 0; mf < 2; mf++) {
            const int c0 = wc * 32 + mf * 16 + r;
            #pragma unroll
            for (int nf = 0; nf < 6; nf++) {
                const int lp = wl * 24 + nf * 4 + q;
                if (lp < lim) {
                    float y0 = acc[mf][nf][0] * al[mf][0];
                    float y1 = acc[mf][nf][1] * al[mf][0];
                    y0 = (y0 > 0.f) ? y0 : pw * y0;
                    y1 = (y1 > 0.f) ? y1 : pw * y1;
                    ob[(size_t)c0 * LOUT_ + lp] = fmaxf(y0, y1);
                    float y2 = acc[mf][nf][2] * al[mf][1];
                    float y3 = acc[mf][nf][3] * al[mf][1];
                    y2 = (y2 > 0.f) ? y2 : pw * y2;
                    y3 = (y3 > 0.f) ? y3 : pw * y3;
                    ob[(size_t)(c0 + 8) * LOUT_ + lp] = fmaxf(y2, y3);
                }
            }
        }

        if (tn < NTILES) convert(tn, SM_B + (uint32_t)((cur ^ 1) * SB_BUF));
        __syncthreads();   // buffer handoff + RAW reuse + sB read-complete
        cur ^= 1;
    }
}

// ---------------- launch ----------------
extern "C" void kernel_launch(void* const* d_in, const int* in_sizes, int n_in,
                              void* d_out, int out_size)
{
    const float* I        = (const float*)d_in[0];
    const float* bn_gamma = (const float*)d_in[1];
    const float* bn_beta  = (const float*)d_in[2];
    const float* bn_mean  = (const float*)d_in[3];
    const float* bn_var   = (const float*)d_in[4];
    const float* conv_w   = (const float*)d_in[5];
    const float* alpha    = (const float*)d_in[6];
    const float* prelu_w  = (const float*)d_in[7];
    float* out = (float*)d_out;

    cudaFuncSetAttribute(bn_bin_conv_pool_v10,
                         cudaFuncAttributeMaxDynamicSharedMemorySize, SM_TOTAL);
    bn_bin_conv_pool_v10<<<GRID, NTHR, SM_TOTAL>>>(
        I, bn_gamma, bn_beta, bn_mean, bn_var, conv_w, alpha, prelu_w, out);
}